// round 2
// baseline (speedup 1.0000x reference)
#include <cuda_runtime.h>
#include <cstddef>

#define Mn   2048
#define LLn  64
#define Pp   4
#define Ssn  2
#define RPB  16
#define NTHR 256
#define NBLK (Mn/RPB)
#define SMEMB ((2*8192 + 16*128) * 4)   /* 64KB wbuf + 8KB hA = 73728 B */

__device__ float g_EWm[(size_t)LLn * Mn * 512];
__device__ float g_EWs[(size_t)LLn * Mn * 512];
__device__ float g_c0[128];
__device__ float g_z1b[512];

typedef unsigned long long u64t;

__device__ __forceinline__ u64t pack2(float x){ u64t r; asm("mov.b64 %0,{%1,%1};":"=l"(r):"f"(x)); return r; }
__device__ __forceinline__ u64t f2u(float a, float b){ u64t r; asm("mov.b64 %0,{%1,%2};":"=l"(r):"f"(a),"f"(b)); return r; }
__device__ __forceinline__ float2 u2f(u64t u){ float2 v; asm("mov.b64 {%0,%1},%2;":"=f"(v.x),"=f"(v.y):"l"(u)); return v; }
__device__ __forceinline__ void fma2(u64t&a, u64t x, u64t w){ asm("fma.rn.f32x2 %0,%1,%2,%0;":"+l"(a):"l"(x),"l"(w)); }

__device__ __forceinline__ void cpa16(float* sdst, const float* gsrc){
  unsigned s=(unsigned)__cvta_generic_to_shared(sdst);
  asm volatile("cp.async.cg.shared.global [%0],[%1],16;"::"r"(s),"l"(gsrc));
}
__device__ __forceinline__ void cpcommit(){ asm volatile("cp.async.commit_group;":::"memory"); }
__device__ __forceinline__ void cpwait1(){ asm volatile("cp.async.wait_group 1;":::"memory"); }
__device__ __forceinline__ void cpwait0(){ asm volatile("cp.async.wait_group 0;":::"memory"); }

__device__ __forceinline__ float sigf(float x){ return 1.f/(1.f+expf(-x)); }

// z layout per thread: acc[j] holds z columns (2cg+64j, 2cg+64j+1), j=0..7.
// gates (i,f,g,o) are 128-wide blocks of the 512 cols:
//   hidden pair p=0 -> dims (2cg,2cg+1):     i=acc[0], f=acc[2], g=acc[4], o=acc[6]
//   hidden pair p=1 -> dims (64+2cg,65+2cg): i=acc[1], f=acc[3], g=acc[5], o=acc[7]
__device__ __forceinline__ void cell2(const u64t z[8], float2 c[2], float2 h[2]){
  #pragma unroll
  for(int p=0;p<2;p++){
    float2 zi=u2f(z[p]), zf=u2f(z[2+p]), zg=u2f(z[4+p]), zo=u2f(z[6+p]);
    float cx = sigf(zf.x)*c[p].x + sigf(zi.x)*tanhf(zg.x);
    float cy = sigf(zf.y)*c[p].y + sigf(zi.y)*tanhf(zg.y);
    c[p].x=cx; c[p].y=cy;
    h[p].x = sigf(zo.x)*tanhf(cx);
    h[p].y = sigf(zo.y)*tanhf(cy);
  }
}

// acc[r][j] += xs[rows 2rg,2rg+1][k] * W[k][cols 2cg+64j .. +1], k=0..127.
// W [128,512] streamed from global in 16x512 tiles, double-buffered cp.async.
__device__ __forceinline__ void gemm_pass(u64t acc[2][8], const float* __restrict__ Wg,
    const float* xs, float* wbuf, int tid, int cg, int rg)
{
  #pragma unroll
  for(int i=0;i<8;i++) cpa16(wbuf + 4*(tid+256*i), Wg + 4*(tid+256*i));
  cpcommit();
  #pragma unroll 1
  for(int kt=0;kt<8;kt++){
    if(kt<7){
      const float* src = Wg + (kt+1)*8192;
      float* dst = wbuf + ((kt+1)&1)*8192;
      #pragma unroll
      for(int i=0;i<8;i++) cpa16(dst + 4*(tid+256*i), src + 4*(tid+256*i));
      cpcommit();
      cpwait1();
    } else {
      cpwait0();
    }
    __syncthreads();
    const float* wb  = wbuf + (kt&1)*8192;
    const float* x0p = xs + (2*rg  )*128 + kt*16;
    const float* x1p = xs + (2*rg+1)*128 + kt*16;
    #pragma unroll
    for(int kk=0;kk<16;kk++){
      u64t x0 = pack2(x0p[kk]);
      u64t x1 = pack2(x1p[kk]);
      const u64t* wrow = (const u64t*)(wb + kk*512) + cg;
      #pragma unroll
      for(int j=0;j<8;j++){
        u64t w = wrow[32*j];
        fma2(acc[0][j], x0, w);
        fma2(acc[1][j], x1, w);
      }
    }
    __syncthreads();
  }
}

__device__ __forceinline__ void acc_from_bias(u64t acc[2][8], const float* b, int cg){
  const float2* bb=(const float2*)b;
  #pragma unroll
  for(int j=0;j<8;j++){ float2 v=bb[cg+32*j]; acc[0][j]=f2u(v.x,v.y); acc[1][j]=acc[0][j]; }
}

__device__ __forceinline__ void store_h(float* hA, int rg, int r, int cg, const float2 hh[2]){
  *(float2*)(hA + (2*rg+r)*128 + 2*cg)      = hh[0];
  *(float2*)(hA + (2*rg+r)*128 + 2*cg + 64) = hh[1];
}

__device__ __forceinline__ void gather_z(u64t a[8], const float* tab, int id, int cg){
  const float2* zr = (const float2*)(tab + (size_t)id*512);
  #pragma unroll
  for(int j=0;j<8;j++){ float2 v=zr[cg+32*j]; a[j]=f2u(v.x,v.y); }
}

__device__ __forceinline__ void write_tab(float* tab, int nid, int cg, const u64t a[8]){
  float2* dr=(float2*)(tab + (size_t)nid*512);
  #pragma unroll
  for(int j=0;j<8;j++) dr[cg+32*j]=u2f(a[j]);
}

__global__ void __launch_bounds__(NTHR,1) layer_kernel(int l, float* __restrict__ emb,
  const int* __restrict__ prop, const int* __restrict__ sup,
  const float* __restrict__ Um, const float* __restrict__ Us,
  const float* __restrict__ Wm, const float* __restrict__ Ws,
  const float* __restrict__ bm, const float* __restrict__ bs)
{
  extern __shared__ float smx[];
  float* wbuf = smx;           // 2 x 16 x 512 floats
  float* hA   = smx + 16384;   // 16 x 128 floats
  const int tid=threadIdx.x, cg=tid&31, rg=tid>>5;
  const int lrow0 = blockIdx.x*RPB;          // layer-local row of this block
  const int base  = l*Mn + lrow0;            // global node id of local row 0

  u64t acc[2][8], zlast[2][8];
  float2 cst[2][2], hh[2];

  // ---- member t=1: z = E_Wm[pid0] + z1b, c_prev = c0
  #pragma unroll
  for(int r=0;r<2;r++){
    int lm = lrow0 + 2*rg + r;
    gather_z(acc[r], g_EWm, prop[lm*Pp+0], cg);
    const float2* zb = (const float2*)g_z1b;
    #pragma unroll
    for(int j=0;j<8;j++){ float2 b=zb[cg+32*j]; float2 a=u2f(acc[r][j]); acc[r][j]=f2u(a.x+b.x, a.y+b.y); }
    cst[r][0] = *(const float2*)(g_c0 + 2*cg);
    cst[r][1] = *(const float2*)(g_c0 + 2*cg + 64);
    cell2(acc[r], cst[r], hh);
    store_h(hA, rg, r, cg, hh);
  }
  __syncthreads();

  // ---- member t=2..4: z = E_Wm[pid_{t-1}] + h @ Um
  #pragma unroll 1
  for(int t=2;t<=4;t++){
    #pragma unroll
    for(int r=0;r<2;r++){
      int lm = lrow0 + 2*rg + r;
      gather_z(acc[r], g_EWm, prop[lm*Pp + (t-1)], cg);
    }
    gemm_pass(acc, Um, hA, wbuf, tid, cg, rg);
    #pragma unroll
    for(int r=0;r<2;r++){ cell2(acc[r], cst[r], hh); store_h(hA, rg, r, cg, hh); }
    __syncthreads();
  }
  // hA == h_m

  // ---- zlast = b_s + h_m @ Ws   (x-contribution of super step t=2)
  acc_from_bias(zlast, bs, cg);
  gemm_pass(zlast, Ws, hA, wbuf, tid, cg, rg);

  // ---- super t=0: z = E_Ws[sid0], zero initial state
  #pragma unroll
  for(int r=0;r<2;r++){
    int lm = lrow0 + 2*rg + r;
    gather_z(acc[r], g_EWs, sup[lm*Ssn+0], cg);
    cst[r][0]=make_float2(0.f,0.f); cst[r][1]=make_float2(0.f,0.f);
    cell2(acc[r], cst[r], hh);
    store_h(hA, rg, r, cg, hh);
  }
  __syncthreads();

  // ---- super t=1: z = E_Ws[sid1] + h @ Us
  #pragma unroll
  for(int r=0;r<2;r++){
    int lm = lrow0 + 2*rg + r;
    gather_z(acc[r], g_EWs, sup[lm*Ssn+1], cg);
  }
  gemm_pass(acc, Us, hA, wbuf, tid, cg, rg);
  #pragma unroll
  for(int r=0;r<2;r++){ cell2(acc[r], cst[r], hh); store_h(hA, rg, r, cg, hh); }
  __syncthreads();

  // ---- super t=2: z = zlast + h @ Us  -> h_s
  gemm_pass(zlast, Us, hA, wbuf, tid, cg, rg);
  #pragma unroll
  for(int r=0;r<2;r++){ cell2(zlast[r], cst[r], hh); store_h(hA, rg, r, cg, hh); }
  __syncthreads();

  // ---- write emb rows (coalesced from smem)
  {
    float4* dst=(float4*)(emb + (size_t)base*128);
    const float4* src=(const float4*)hA;
    #pragma unroll
    for(int i=0;i<2;i++) dst[tid+256*i]=src[tid+256*i];
  }

  // ---- produce z-tables for this layer's rows
  acc_from_bias(acc, bm, cg);
  gemm_pass(acc, Wm, hA, wbuf, tid, cg, rg);
  #pragma unroll
  for(int r=0;r<2;r++) write_tab(g_EWm, base + 2*rg + r, cg, acc[r]);

  acc_from_bias(acc, bs, cg);
  gemm_pass(acc, Ws, hA, wbuf, tid, cg, rg);
  #pragma unroll
  for(int r=0;r<2;r++) write_tab(g_EWs, base + 2*rg + r, cg, acc[r]);
}

__global__ void __launch_bounds__(NTHR,1) layer0_kernel(float* __restrict__ emb,
  const int* __restrict__ names, const float* __restrict__ btab,
  const float* __restrict__ Wm, const float* __restrict__ Ws,
  const float* __restrict__ bm, const float* __restrict__ bs)
{
  extern __shared__ float smx[];
  float* wbuf=smx; float* hA=smx+16384;
  const int tid=threadIdx.x, cg=tid&31, rg=tid>>5;
  const int row0 = blockIdx.x*RPB;

  for(int i=tid;i<RPB*128;i+=NTHR){
    int r=i>>7, k=i&127;
    float v = btab[names[row0+r]*128 + k];
    hA[i]=v;
    emb[(size_t)(row0+r)*128 + k]=v;
  }
  __syncthreads();

  u64t acc[2][8];
  acc_from_bias(acc, bm, cg);
  gemm_pass(acc, Wm, hA, wbuf, tid, cg, rg);
  #pragma unroll
  for(int r=0;r<2;r++) write_tab(g_EWm, row0 + 2*rg + r, cg, acc[r]);

  acc_from_bias(acc, bs, cg);
  gemm_pass(acc, Ws, hA, wbuf, tid, cg, rg);
  #pragma unroll
  for(int r=0;r<2;r++) write_tab(g_EWs, row0 + 2*rg + r, cg, acc[r]);
}

// One-shot constants: z0 = em@Wm + bm -> c0, h0 -> z1b = h0@Um
__global__ void init_kernel(const float* __restrict__ em, const float* __restrict__ Wm,
                            const float* __restrict__ Um, const float* __restrict__ bm)
{
  __shared__ float z0[512]; __shared__ float h0[128]; __shared__ float ems[128];
  int t=threadIdx.x;
  if(t<128) ems[t]=em[t];
  __syncthreads();
  float s=bm[t];
  for(int k=0;k<128;k++) s += ems[k]*Wm[k*512+t];
  z0[t]=s;
  __syncthreads();
  if(t<128){
    float zi=z0[t], zg=z0[256+t], zo=z0[384+t];
    float c = (1.f/(1.f+expf(-zi)))*tanhf(zg);
    g_c0[t]=c;
    h0[t]=(1.f/(1.f+expf(-zo)))*tanhf(c);
  }
  __syncthreads();
  float s2=0.f;
  for(int k=0;k<128;k++) s2 += h0[k]*Um[k*512+t];
  g_z1b[t]=s2;
}

extern "C" void kernel_launch(void* const* d_in, const int* in_sizes, int n_in,
                              void* d_out, int out_size)
{
  const int*   names=(const int*)d_in[0];
  const int*   prop =(const int*)d_in[1];
  const int*   sup  =(const int*)d_in[2];
  const float* btab =(const float*)d_in[3];
  const float* Wm   =(const float*)d_in[4];
  const float* Um   =(const float*)d_in[5];
  const float* bm   =(const float*)d_in[6];
  const float* Ws   =(const float*)d_in[7];
  const float* Us   =(const float*)d_in[8];
  const float* bs   =(const float*)d_in[9];
  const float* em   =(const float*)d_in[10];
  float* emb=(float*)d_out;

  cudaFuncSetAttribute(layer_kernel,  cudaFuncAttributeMaxDynamicSharedMemorySize, SMEMB);
  cudaFuncSetAttribute(layer0_kernel, cudaFuncAttributeMaxDynamicSharedMemorySize, SMEMB);

  init_kernel<<<1,512>>>(em, Wm, Um, bm);
  layer0_kernel<<<NBLK,NTHR,SMEMB>>>(emb, names, btab, Wm, Ws, bm, bs);
  for(int l=1;l<LLn;l++)
    layer_kernel<<<NBLK,NTHR,SMEMB>>>(l, emb,
        prop + (size_t)l*Mn*Pp, sup + (size_t)l*Mn*Ssn,
        Um, Us, Wm, Ws, bm, bs);
}

// round 3
// speedup vs baseline: 1.2046x; 1.2046x over previous
#include <cuda_runtime.h>
#include <cstddef>

#define Mn   2048
#define LLn  64
#define Pp   4
#define Ssn  2
#define RPB  16
#define NTHR 256
#define NBLK (Mn/RPB)
#define SMEMB ((2*8192 + 16*128) * 4)   /* 64KB wbuf + 8KB hA = 73728 B */

__device__ float g_EWm[(size_t)LLn * Mn * 512];
__device__ float g_EWs[(size_t)LLn * Mn * 512];
__device__ float g_c0[128];
__device__ float g_z1b[512];

typedef unsigned long long u64t;

__device__ __forceinline__ u64t pack2(float x){ u64t r; asm("mov.b64 %0,{%1,%1};":"=l"(r):"f"(x)); return r; }
__device__ __forceinline__ u64t f2u(float a, float b){ u64t r; asm("mov.b64 %0,{%1,%2};":"=l"(r):"f"(a),"f"(b)); return r; }
__device__ __forceinline__ float2 u2f(u64t u){ float2 v; asm("mov.b64 {%0,%1},%2;":"=f"(v.x),"=f"(v.y):"l"(u)); return v; }
__device__ __forceinline__ void fma2(u64t&a, u64t x, u64t w){ asm("fma.rn.f32x2 %0,%1,%2,%0;":"+l"(a):"l"(x),"l"(w)); }

__device__ __forceinline__ void cpa16(float* sdst, const float* gsrc){
  unsigned s=(unsigned)__cvta_generic_to_shared(sdst);
  asm volatile("cp.async.cg.shared.global [%0],[%1],16;"::"r"(s),"l"(gsrc));
}
__device__ __forceinline__ void cpcommit(){ asm volatile("cp.async.commit_group;":::"memory"); }
__device__ __forceinline__ void cpwait1(){ asm volatile("cp.async.wait_group 1;":::"memory"); }
__device__ __forceinline__ void cpwait0(){ asm volatile("cp.async.wait_group 0;":::"memory"); }

__device__ __forceinline__ float sigf(float x){ return 1.f/(1.f+__expf(-x)); }
__device__ __forceinline__ float tfast(float x){
  x = fminf(fmaxf(x,-15.f),15.f);
  float t = __expf(2.f*x);
  return (t-1.f)/(t+1.f);
}

// Thread layout: 8 warps = 4 teams x 2 warps. team=wid>>1 owns rows 4*team..+3.
// Warp wsub covers hidden dims [64*wsub, 64*wsub+64); lane cg owns dims
// d=64*wsub+2*cg, d+1. Gate g z-columns at float offset co(g)=128*g+64*wsub+2*cg.
// acc[r][g] : u64 = z[d..d+1] of gate g, row (4*team+r).

// acc[r][g] += xs[row][k] * W[k][cols], k=0..127. W [128,512] streamed from
// global in 16x512 tiles, double-buffered via cp.async.
__device__ __forceinline__ void gemm_pass(u64t acc[4][4], const float* __restrict__ Wg,
    const float* xs, float* wbuf, int tid, int co0, int tr0)
{
  #pragma unroll
  for(int i=0;i<8;i++) cpa16(wbuf + 4*(tid+256*i), Wg + 4*(tid+256*i));
  cpcommit();
  #pragma unroll 1
  for(int kt=0;kt<8;kt++){
    if(kt<7){
      const float* src = Wg + (kt+1)*8192;
      float* dst = wbuf + ((kt+1)&1)*8192;
      #pragma unroll
      for(int i=0;i<8;i++) cpa16(dst + 4*(tid+256*i), src + 4*(tid+256*i));
      cpcommit(); cpwait1();
    } else {
      cpwait0();
    }
    __syncthreads();
    const float* wb = wbuf + (kt&1)*8192;
    #pragma unroll
    for(int kb=0;kb<4;kb++){
      float4 xr[4];
      #pragma unroll
      for(int r=0;r<4;r++)
        xr[r] = *(const float4*)(xs + (tr0+r)*128 + kt*16 + kb*4);
      #pragma unroll
      for(int kq=0;kq<4;kq++){
        const float* wrow = wb + (kb*4+kq)*512 + co0;
        u64t w0 = *(const u64t*)(wrow      );
        u64t w1 = *(const u64t*)(wrow + 128);
        u64t w2 = *(const u64t*)(wrow + 256);
        u64t w3 = *(const u64t*)(wrow + 384);
        #pragma unroll
        for(int r=0;r<4;r++){
          u64t xv = pack2((&xr[r].x)[kq]);
          fma2(acc[r][0], xv, w0);
          fma2(acc[r][1], xv, w1);
          fma2(acc[r][2], xv, w2);
          fma2(acc[r][3], xv, w3);
        }
      }
    }
    __syncthreads();
  }
}

// LSTM cell for one row's dim-pair: z (i,f,g,o) -> updates c, returns h.
__device__ __forceinline__ float2 cell1(const u64t z[4], float2& c){
  float2 zi=u2f(z[0]), zf=u2f(z[1]), zg=u2f(z[2]), zo=u2f(z[3]);
  c.x = sigf(zf.x)*c.x + sigf(zi.x)*tfast(zg.x);
  c.y = sigf(zf.y)*c.y + sigf(zi.y)*tfast(zg.y);
  float2 h;
  h.x = sigf(zo.x)*tfast(c.x);
  h.y = sigf(zo.y)*tfast(c.y);
  return h;
}

__device__ __forceinline__ void acc_from_bias(u64t acc[4][4], const float* b, int co0){
  #pragma unroll
  for(int g=0;g<4;g++){
    float2 v = *(const float2*)(b + co0 + 128*g);
    u64t u = f2u(v.x,v.y);
    #pragma unroll
    for(int r=0;r<4;r++) acc[r][g]=u;
  }
}

__device__ __forceinline__ void gather_row(u64t a[4], const float* tab, int id, int co0){
  const float* base = tab + (size_t)id*512 + co0;
  #pragma unroll
  for(int g=0;g<4;g++){ float2 v=*(const float2*)(base + 128*g); a[g]=f2u(v.x,v.y); }
}

__device__ __forceinline__ void write_row(float* tab, int nid, int co0, const u64t a[4]){
  float* base = tab + (size_t)nid*512 + co0;
  #pragma unroll
  for(int g=0;g<4;g++) *(float2*)(base + 128*g) = u2f(a[g]);
}

__global__ void __launch_bounds__(NTHR,1) layer_kernel(int l, float* __restrict__ emb,
  const int* __restrict__ prop, const int* __restrict__ sup,
  const float* __restrict__ Um, const float* __restrict__ Us,
  const float* __restrict__ Wm, const float* __restrict__ Ws,
  const float* __restrict__ bm, const float* __restrict__ bs)
{
  extern __shared__ float smx[];
  float* wbuf = smx;           // 2 x 16 x 512 floats
  float* hA   = smx + 16384;   // 16 x 128 floats
  const int tid=threadIdx.x, cg=tid&31, wid=tid>>5;
  const int team=wid>>1, wsub=wid&1;
  const int co0 = 64*wsub + 2*cg;
  const int tr0 = 4*team;
  const int lrow0 = blockIdx.x*RPB;
  const int base  = l*Mn + lrow0;

  u64t acc[4][4], zlast[4][4];
  float2 cst[4];

  // ---- member t=1: z = E_Wm[pid0] + z1b, c_prev = c0
  {
    float2 zb[4];
    #pragma unroll
    for(int g=0;g<4;g++) zb[g] = *(const float2*)(g_z1b + co0 + 128*g);
    float2 c0v = *(const float2*)(g_c0 + co0);
    #pragma unroll
    for(int r=0;r<4;r++){
      gather_row(acc[r], g_EWm, prop[(lrow0+tr0+r)*Pp+0], co0);
      #pragma unroll
      for(int g=0;g<4;g++){ float2 a=u2f(acc[r][g]); acc[r][g]=f2u(a.x+zb[g].x, a.y+zb[g].y); }
      cst[r] = c0v;
      *(float2*)(hA + (tr0+r)*128 + co0) = cell1(acc[r], cst[r]);
    }
  }
  __syncthreads();

  // ---- member t=2..4: z = E_Wm[pid_{t-1}] + h @ Um
  #pragma unroll 1
  for(int t=2;t<=4;t++){
    #pragma unroll
    for(int r=0;r<4;r++)
      gather_row(acc[r], g_EWm, prop[(lrow0+tr0+r)*Pp + (t-1)], co0);
    gemm_pass(acc, Um, hA, wbuf, tid, co0, tr0);
    #pragma unroll
    for(int r=0;r<4;r++)
      *(float2*)(hA + (tr0+r)*128 + co0) = cell1(acc[r], cst[r]);
    __syncthreads();
  }
  // hA == h_m

  // ---- zlast = b_s + h_m @ Ws   (x-contribution of super step t=2)
  acc_from_bias(zlast, bs, co0);
  gemm_pass(zlast, Ws, hA, wbuf, tid, co0, tr0);

  // ---- super t=0: z = E_Ws[sid0], zero initial state
  #pragma unroll
  for(int r=0;r<4;r++){
    gather_row(acc[r], g_EWs, sup[(lrow0+tr0+r)*Ssn+0], co0);
    cst[r]=make_float2(0.f,0.f);
    *(float2*)(hA + (tr0+r)*128 + co0) = cell1(acc[r], cst[r]);
  }
  __syncthreads();

  // ---- super t=1: z = E_Ws[sid1] + h @ Us
  #pragma unroll
  for(int r=0;r<4;r++)
    gather_row(acc[r], g_EWs, sup[(lrow0+tr0+r)*Ssn+1], co0);
  gemm_pass(acc, Us, hA, wbuf, tid, co0, tr0);
  #pragma unroll
  for(int r=0;r<4;r++)
    *(float2*)(hA + (tr0+r)*128 + co0) = cell1(acc[r], cst[r]);
  __syncthreads();

  // ---- super t=2: z = zlast + h @ Us  -> h_s
  gemm_pass(zlast, Us, hA, wbuf, tid, co0, tr0);
  #pragma unroll
  for(int r=0;r<4;r++)
    *(float2*)(hA + (tr0+r)*128 + co0) = cell1(zlast[r], cst[r]);
  __syncthreads();

  // ---- write emb rows (coalesced from smem)
  {
    float4* dst=(float4*)(emb + (size_t)base*128);
    const float4* src=(const float4*)hA;
    #pragma unroll
    for(int i=0;i<2;i++) dst[tid+256*i]=src[tid+256*i];
  }

  // ---- produce z-tables for this layer's rows
  acc_from_bias(acc, bm, co0);
  gemm_pass(acc, Wm, hA, wbuf, tid, co0, tr0);
  #pragma unroll
  for(int r=0;r<4;r++) write_row(g_EWm, base + tr0 + r, co0, acc[r]);

  acc_from_bias(acc, bs, co0);
  gemm_pass(acc, Ws, hA, wbuf, tid, co0, tr0);
  #pragma unroll
  for(int r=0;r<4;r++) write_row(g_EWs, base + tr0 + r, co0, acc[r]);
}

__global__ void __launch_bounds__(NTHR,1) layer0_kernel(float* __restrict__ emb,
  const int* __restrict__ names, const float* __restrict__ btab,
  const float* __restrict__ Wm, const float* __restrict__ Ws,
  const float* __restrict__ bm, const float* __restrict__ bs)
{
  extern __shared__ float smx[];
  float* wbuf=smx; float* hA=smx+16384;
  const int tid=threadIdx.x, cg=tid&31, wid=tid>>5;
  const int team=wid>>1, wsub=wid&1;
  const int co0 = 64*wsub + 2*cg;
  const int tr0 = 4*team;
  const int row0 = blockIdx.x*RPB;

  for(int i=tid;i<RPB*128;i+=NTHR){
    int r=i>>7, k=i&127;
    float v = btab[names[row0+r]*128 + k];
    hA[i]=v;
    emb[(size_t)(row0+r)*128 + k]=v;
  }
  __syncthreads();

  u64t acc[4][4];
  acc_from_bias(acc, bm, co0);
  gemm_pass(acc, Wm, hA, wbuf, tid, co0, tr0);
  #pragma unroll
  for(int r=0;r<4;r++) write_row(g_EWm, row0 + tr0 + r, co0, acc[r]);

  acc_from_bias(acc, bs, co0);
  gemm_pass(acc, Ws, hA, wbuf, tid, co0, tr0);
  #pragma unroll
  for(int r=0;r<4;r++) write_row(g_EWs, row0 + tr0 + r, co0, acc[r]);
}

// One-shot constants: z0 = em@Wm + bm -> c0, h0 -> z1b = h0@Um
__global__ void init_kernel(const float* __restrict__ em, const float* __restrict__ Wm,
                            const float* __restrict__ Um, const float* __restrict__ bm)
{
  __shared__ float z0[512]; __shared__ float h0[128]; __shared__ float ems[128];
  int t=threadIdx.x;
  if(t<128) ems[t]=em[t];
  __syncthreads();
  float s=bm[t];
  for(int k=0;k<128;k++) s += ems[k]*Wm[k*512+t];
  z0[t]=s;
  __syncthreads();
  if(t<128){
    float zi=z0[t], zg=z0[256+t], zo=z0[384+t];
    float c = (1.f/(1.f+expf(-zi)))*tanhf(zg);
    g_c0[t]=c;
    h0[t]=(1.f/(1.f+expf(-zo)))*tanhf(c);
  }
  __syncthreads();
  float s2=0.f;
  for(int k=0;k<128;k++) s2 += h0[k]*Um[k*512+t];
  g_z1b[t]=s2;
}

extern "C" void kernel_launch(void* const* d_in, const int* in_sizes, int n_in,
                              void* d_out, int out_size)
{
  const int*   names=(const int*)d_in[0];
  const int*   prop =(const int*)d_in[1];
  const int*   sup  =(const int*)d_in[2];
  const float* btab =(const float*)d_in[3];
  const float* Wm   =(const float*)d_in[4];
  const float* Um   =(const float*)d_in[5];
  const float* bm   =(const float*)d_in[6];
  const float* Ws   =(const float*)d_in[7];
  const float* Us   =(const float*)d_in[8];
  const float* bs   =(const float*)d_in[9];
  const float* em   =(const float*)d_in[10];
  float* emb=(float*)d_out;

  cudaFuncSetAttribute(layer_kernel,  cudaFuncAttributeMaxDynamicSharedMemorySize, SMEMB);
  cudaFuncSetAttribute(layer0_kernel, cudaFuncAttributeMaxDynamicSharedMemorySize, SMEMB);

  init_kernel<<<1,512>>>(em, Wm, Um, bm);
  layer0_kernel<<<NBLK,NTHR,SMEMB>>>(emb, names, btab, Wm, Ws, bm, bs);
  for(int l=1;l<LLn;l++)
    layer_kernel<<<NBLK,NTHR,SMEMB>>>(l, emb,
        prop + (size_t)l*Mn*Pp, sup + (size_t)l*Mn*Ssn,
        Um, Us, Wm, Ws, bm, bs);
}